// round 17
// baseline (speedup 1.0000x reference)
#include <cuda_runtime.h>

// Path signature, depth 3 — THREE i-planes per block, all-producer balance.
// path: (32, 128, 48) fp32. Out per batch: [48 | 2304 | 110592] = 112944.
//
// S3[i,j,k] = sum_t w[i][t][j] * v[t][k]
//   v[t][j]    = path[t+1][j] - path[t][j]
//   w[i][t][j] = S2prev[i][j] + (0.5*S1prev[i] + v[t][i]/6) * v[t][j]
//   S2[i][j]  += (S1prev[i] + 0.5*v[t][i]) * v[t][j]
//
// Block (bx,b): planes i = 3bx + {0,1,2}. 144 threads.
// Phase A: ALL threads produce (r = tid/48 -> plane, jj = tid%48); group
// r==0 also writes v. Perfectly uniform per-stage issue work.
// Phase B: 12(j) x 12(k) grid, per-thread 4j x 4k x 3 planes = 24 u64
// f32x2 accumulators (paired along j; w pairs free from 16B shared loads,
// one shared v float4 serves all 3 planes -> 0.89 B LDS per lane-FMA).
// TCH=16 double-buffered stages, producers one chunk ahead, one barrier
// per stage. 24KB path block staged in shared (LDS-fed producer chain).

#define NB     32
#define LPATH  128
#define C      48
#define NSTEPS (LPATH - 1)          // 127
#define LVL2   (C * C)
#define STR    (C + LVL2 + C * C * C)   // 112944
#define OFF2   C
#define OFF3   (C + LVL2)
#define TCH    16
#define NFULL  7                        // 7 full chunks of 16 = 112
#define TAILT  (NSTEPS - NFULL * TCH)   // 15

typedef unsigned long long u64;

__device__ __forceinline__ void ffma2(u64& d, u64 a, u64 b) {
    asm("fma.rn.f32x2 %0, %1, %2, %0;" : "+l"(d) : "l"(a), "l"(b));
}
__device__ __forceinline__ u64 dup_f32(float x) {
    u64 r;
    asm("mov.b64 %0, {%1, %1};" : "=l"(r) : "f"(x));
    return r;
}
__device__ __forceinline__ float2 unpk(u64 a) {
    float2 r;
    asm("mov.b64 {%0, %1}, %2;" : "=f"(r.x), "=f"(r.y) : "l"(a));
    return r;
}

// Phase A: every thread produces the w row for its plane r; group 0 also v.
template<int T>
__device__ __forceinline__ void phase_a(
    const float* __restrict__ sp, int base_t, int buf, int i_r, int r, int jj,
    float& p_j, float& p_i, float p0_i, float& S2,
    float (*sh_v)[TCH][C], float (*sh_w)[3][TCH][C])
{
#pragma unroll
    for (int t = 0; t < T; ++t) {
        const float pn_j = sp[(base_t + t + 1) * C + jj];  // LDS, stride-1
        const float pn_i = sp[(base_t + t + 1) * C + i_r]; // LDS broadcast
        const float v_j = pn_j - p_j;
        const float v_i = pn_i - p_i;
        const float s1  = p_i - p0_i;
        if (r == 0) sh_v[buf][t][jj] = v_j;
        sh_w[buf][r][t][jj] = fmaf(fmaf(1.0f / 6.0f, v_i, 0.5f * s1), v_j, S2);
        S2 = fmaf(fmaf(0.5f, v_i, s1), v_j, S2);
        p_j = pn_j;
        p_i = pn_i;
    }
}

// Phase B: all threads, T rank-1 updates of the three 4x4 tiles.
template<int T>
__device__ __forceinline__ void phase_b(
    int buf, int j0, int k0, u64 (&acc)[3][2][4],
    float (*sh_v)[TCH][C], float (*sh_w)[3][TCH][C])
{
#pragma unroll 2
    for (int t = 0; t < T; ++t) {
        const ulonglong2 w0 = *(const ulonglong2*)&sh_w[buf][0][t][j0];
        const ulonglong2 w1 = *(const ulonglong2*)&sh_w[buf][1][t][j0];
        const ulonglong2 w2 = *(const ulonglong2*)&sh_w[buf][2][t][j0];
        const float4     vv = *(const float4*)&sh_v[buf][t][k0];
        const u64 vp[4] = { dup_f32(vv.x), dup_f32(vv.y),
                            dup_f32(vv.z), dup_f32(vv.w) };
        const u64 wa[3][2] = { { w0.x, w0.y }, { w1.x, w1.y }, { w2.x, w2.y } };
#pragma unroll
        for (int pl = 0; pl < 3; ++pl)
#pragma unroll
            for (int jp = 0; jp < 2; ++jp)
#pragma unroll
                for (int kx = 0; kx < 4; ++kx)
                    ffma2(acc[pl][jp][kx], wa[pl][jp], vp[kx]);
    }
}

__global__ __launch_bounds__(144, 4)
void sig_depth3_kernel(const float* __restrict__ path, float* __restrict__ out)
{
    const int bx  = blockIdx.x;   // 0..15 -> planes 3bx + {0,1,2}
    const int b   = blockIdx.y;   // 0..31
    const int tid = threadIdx.x;  // 0..143

    __shared__ __align__(16) float sp[LPATH * C];        // 24KB path block
    __shared__ __align__(16) float sh_v[2][TCH][C];      // 6KB
    __shared__ __align__(16) float sh_w[2][3][TCH][C];   // 18KB

    const float* pb = path + (size_t)b * LPATH * C;

    // ---- Stage the path block into shared (coalesced float4) ----
    {
        const float4* src = (const float4*)pb;
        float4* dst = (float4*)sp;
#pragma unroll
        for (int idx = tid; idx < (LPATH * C) / 4; idx += 144)
            dst[idx] = src[idx];
    }

    u64 acc[3][2][4];
#pragma unroll
    for (int pl = 0; pl < 3; ++pl)
#pragma unroll
        for (int jp = 0; jp < 2; ++jp)
#pragma unroll
            for (int kx = 0; kx < 4; ++kx) acc[pl][jp][kx] = 0ull;

    const int j0 = (tid / 12) * 4;   // 0,4,...,44
    const int k0 = (tid % 12) * 4;   // 0,4,...,44

    // Producer identity: ALL threads produce. r = plane index within block.
    const int r   = tid / C;         // 0,1,2
    const int jj  = tid - r * C;     // 0..47
    const int i_r = 3 * bx + r;

    __syncthreads();   // path staged before any phase-A read

    float p_j  = sp[jj];
    float p0_i = sp[i_r];
    float p_i  = p0_i;
    float S2   = 0.0f;

    // ---- Pipelined mainloop: A(s+1) before B(s), one barrier per stage ----
    phase_a<TCH>(sp, 0, 0, i_r, r, jj, p_j, p_i, p0_i, S2, sh_v, sh_w);
    __syncthreads();

#pragma unroll 1
    for (int s = 0; s < NFULL - 1; ++s) {     // s = 0..5
        phase_a<TCH>(sp, (s + 1) * TCH, (s + 1) & 1, i_r, r, jj,
                     p_j, p_i, p0_i, S2, sh_v, sh_w);
        phase_b<TCH>(s & 1, j0, k0, acc, sh_v, sh_w);
        __syncthreads();
    }
    // s = 6: produce tail chunk (15 steps) into buf 1, consume chunk 6.
    phase_a<TAILT>(sp, NFULL * TCH, NFULL & 1, i_r, r, jj,
                   p_j, p_i, p0_i, S2, sh_v, sh_w);
    phase_b<TCH>((NFULL - 1) & 1, j0, k0, acc, sh_v, sh_w);
    __syncthreads();
    phase_b<TAILT>(NFULL & 1, j0, k0, acc, sh_v, sh_w);

    // ---- Epilogue ----
    float* ob = out + (size_t)b * STR;

#pragma unroll
    for (int pl = 0; pl < 3; ++pl) {
        float* o3 = ob + OFF3 + (size_t)(3 * bx + pl) * LVL2;
#pragma unroll
        for (int jp = 0; jp < 2; ++jp) {
            const float2 a0 = unpk(acc[pl][jp][0]);
            const float2 a1 = unpk(acc[pl][jp][1]);
            const float2 a2 = unpk(acc[pl][jp][2]);
            const float2 a3 = unpk(acc[pl][jp][3]);
            const int jlo = j0 + 2 * jp, jhi = jlo + 1;
            *(float4*)&o3[jlo * C + k0] = make_float4(a0.x, a1.x, a2.x, a3.x);
            *(float4*)&o3[jhi * C + k0] = make_float4(a0.y, a1.y, a2.y, a3.y);
        }
    }

    // Levels 1-2: every thread owns one (i_r, jj) cell.
    ob[OFF2 + i_r * C + jj] = S2;
    if (bx == 0 && r == 0) {
        // p_j now holds path[b][127][jj]
        ob[jj] = p_j - sp[jj];
    }
}

extern "C" void kernel_launch(void* const* d_in, const int* in_sizes, int n_in,
                              void* d_out, int out_size)
{
    (void)in_sizes; (void)n_in; (void)out_size;
    const float* path = (const float*)d_in[0];
    float* out = (float*)d_out;
    dim3 grid(C / 3, NB);   // (i-triples, batch) = (16, 32)
    dim3 block(144);
    sig_depth3_kernel<<<grid, block>>>(path, out);
}